// round 3
// baseline (speedup 1.0000x reference)
#include <cuda_runtime.h>
#include <cuda_fp16.h>
#include <cstdint>
#include <cmath>

constexpr int BATCH = 8;
constexpr int SEQ   = 4096;
constexpr int DIM   = 768;
constexpr int NST   = 16;
constexpr int ROWS  = BATCH * SEQ;        // 32768
constexpr int CHUNK = 64;
constexpr int NCHUNK = SEQ / CHUNK;       // 64
constexpr int NTASK  = BATCH * NCHUNK;    // 512

// device scratch (allocations forbidden)
__device__ float  d_gu[ROWS * NST];
__device__ float  d_lend[NTASK * NST];
__device__ float  d_hstart[NTASK * NST];
__device__ float  d_Ppow[CHUNK * NST * NST];
__device__ __half d_xh[ROWS * DIM];           // 48 MB fp16 x
__device__ __half d_wsk[DIM * DIM];           // fp16 W_skip
__device__ __half d_wio[2 * NST * DIM];       // rows 0-15 W_in, 16-31 W_gate

#define DEVI __device__ __forceinline__

DEVI uint32_t smem_u32(const void* p) {
    uint32_t a;
    asm("{ .reg .u64 t; cvta.to.shared.u64 t, %1; cvt.u32.u64 %0, t; }" : "=r"(a) : "l"(p));
    return a;
}
DEVI void cpa16(uint32_t dst, const void* src) {
    asm volatile("cp.async.ca.shared.global [%0], [%1], 16;" :: "r"(dst), "l"(src));
}
DEVI void cpa_commit() { asm volatile("cp.async.commit_group;"); }
DEVI void cpa_wait1()  { asm volatile("cp.async.wait_group 1;"); }
DEVI void ldm4(uint32_t* r, uint32_t a) {
    asm volatile("ldmatrix.sync.aligned.m8n8.x4.shared.b16 {%0,%1,%2,%3}, [%4];"
                 : "=r"(r[0]), "=r"(r[1]), "=r"(r[2]), "=r"(r[3]) : "r"(a));
}
DEVI void mma16816(float* c, const uint32_t* a, uint32_t b0, uint32_t b1) {
    asm volatile(
        "mma.sync.aligned.m16n8k16.row.col.f32.f16.f16.f32 "
        "{%0,%1,%2,%3},{%4,%5,%6,%7},{%8,%9},{%0,%1,%2,%3};"
        : "+f"(c[0]), "+f"(c[1]), "+f"(c[2]), "+f"(c[3])
        : "r"(a[0]), "r"(a[1]), "r"(a[2]), "r"(a[3]), "r"(b0), "r"(b1));
}

// --------------------------------------------------------------------------
// fp32 -> fp16 conversion (vectorized, grid-stride)
// --------------------------------------------------------------------------
__global__ void __launch_bounds__(256) k_tohalf(const float* __restrict__ s,
                                                __half* __restrict__ d, int n4) {
    int i = blockIdx.x * 256 + threadIdx.x;
    if (i < n4) {
        float4 v = ((const float4*)s)[i];
        __half2 h0 = __floats2half2_rn(v.x, v.y);
        __half2 h1 = __floats2half2_rn(v.z, v.w);
        ((__half2*)d)[2 * i]     = h0;
        ((__half2*)d)[2 * i + 1] = h1;
    }
}

// --------------------------------------------------------------------------
// T-matrix powers: Ppow[j] = T^(j+1); T[n][m] = sigma(a[n])*delta + (V U^T)[m][n]... 
// T[n][m] = sigma(a[n]) delta(n,m) + sum_r V[m,r] U[n,r]  (h_new = h*a + h @ lowrank^T)
// --------------------------------------------------------------------------
__global__ void __launch_bounds__(256) k_powers(const float* __restrict__ a_logit,
                                                const float* __restrict__ U,
                                                const float* __restrict__ V) {
    __shared__ float Ts[256], cur[256];
    int t = threadIdx.x, n = t >> 4, m = t & 15;
    float acc = 0.f;
#pragma unroll
    for (int r = 0; r < 8; r++) acc += V[m * 8 + r] * U[n * 8 + r];
    if (m == n) acc += 1.f / (1.f + expf(-a_logit[n]));
    Ts[t] = acc; cur[t] = acc; d_Ppow[t] = acc;
    __syncthreads();
    for (int j = 1; j < CHUNK; j++) {
        float s = 0.f;
#pragma unroll
        for (int q = 0; q < 16; q++) s += Ts[n * 16 + q] * cur[q * 16 + m];
        __syncthreads();
        cur[t] = s; d_Ppow[j * 256 + t] = s;
        __syncthreads();
    }
}

// --------------------------------------------------------------------------
// per-chunk local scan (h0 = 0), in place; chunk-final states to d_lend
// --------------------------------------------------------------------------
__global__ void __launch_bounds__(256) k_scan_local() {
    int tid = threadIdx.x;
    int task = blockIdx.x * 16 + (tid >> 4);
    int n = tid & 15;
    float Trow[16];
#pragma unroll
    for (int m = 0; m < 16; m++) Trow[m] = d_Ppow[n * 16 + m];
    int b = task >> 6, k = task & 63;
    float* g = d_gu + ((size_t)(b * SEQ + k * CHUNK)) * NST;
    float h = 0.f;
    for (int j = 0; j < CHUNK; j++) {
        float hn = g[j * NST + n];
#pragma unroll
        for (int m = 0; m < 16; m++)
            hn += Trow[m] * __shfl_sync(0xffffffffu, h, m, 16);
        h = hn;
        g[j * NST + n] = h;
    }
    d_lend[task * NST + n] = h;
}

__global__ void __launch_bounds__(128) k_scan_boundary() {
    int tid = threadIdx.x;
    int b = tid >> 4, n = tid & 15;
    float TC[16];
#pragma unroll
    for (int m = 0; m < 16; m++) TC[m] = d_Ppow[(CHUNK - 1) * 256 + n * 16 + m];
    float s = 0.f;
    for (int k = 0; k < NCHUNK; k++) {
        int base = (b * NCHUNK + k) * NST;
        d_hstart[base + n] = s;
        float acc = d_lend[base + n];
#pragma unroll
        for (int m = 0; m < 16; m++)
            acc += TC[m] * __shfl_sync(0xffffffffu, s, m, 16);
        s = acc;
    }
}

__global__ void __launch_bounds__(256) k_fixup() {
    int idx = blockIdx.x * 256 + threadIdx.x;
    int r = idx >> 4, n = idx & 15;
    int b = r >> 12, t = r & 4095;
    int k = t >> 6, j = t & 63;
    const float* P = d_Ppow + j * 256 + n * 16;
    const float* s = d_hstart + (b * NCHUNK + k) * NST;
    float acc = d_gu[idx];
#pragma unroll
    for (int m = 0; m < 16; m++) acc += P[m] * s[m];
    d_gu[idx] = acc;
}

// --------------------------------------------------------------------------
// GEMM1: gu = sigmoid(x Wg^T + bg) * (x Wi^T + bi)
// CTA: M=128, N=32, K chunks of 32 (24 chunks), 8 warps (16 rows each)
// --------------------------------------------------------------------------
constexpr int AST = 40;   // padded row stride in halves (80B)

__global__ void __launch_bounds__(256) k_gemm1(const float* __restrict__ bin,
                                               const float* __restrict__ bgate) {
    __shared__ __half sA[2][128 * AST];
    __shared__ __half sB[2][32 * AST];
    __shared__ float sb[32];
    int tid = threadIdx.x, w = tid >> 5, l = tid & 31;
    int mt = blockIdx.x;
    if (tid < 16) { sb[tid] = bin[tid]; sb[16 + tid] = bgate[tid]; }

    uint32_t aAddr = smem_u32(sA), bAddr = smem_u32(sB);
    const __half* Asrc = d_xh + (size_t)mt * 128 * DIM;

    auto load_stage = [&](int kc) {
        __half* Ad = sA[kc & 1];
        // A: 512 segs of 8 halves
#pragma unroll
        for (int q = 0; q < 2; q++) {
            int s = tid + q * 256;
            int row = s >> 2, cs = s & 3;
            cpa16(smem_u32(Ad + row * AST + cs * 8),
                  Asrc + (size_t)row * DIM + kc * 32 + cs * 8);
        }
        // B: 128 segs
        if (tid < 128) {
            int row = tid >> 2, cs = tid & 3;
            cpa16(smem_u32(sB[kc & 1] + row * AST + cs * 8),
                  d_wio + (size_t)row * DIM + kc * 32 + cs * 8);
        }
    };

    float c[4][4];
#pragma unroll
    for (int i = 0; i < 4; i++)
#pragma unroll
        for (int j = 0; j < 4; j++) c[i][j] = 0.f;

    load_stage(0);
    cpa_commit();
    for (int kc = 0; kc < 24; kc++) {
        if (kc + 1 < 24) load_stage(kc + 1);
        cpa_commit();
        cpa_wait1();
        __syncthreads();
        uint32_t Ab = aAddr + (kc & 1) * (128 * AST * 2);
        uint32_t Bb = bAddr + (kc & 1) * (32 * AST * 2);
#pragma unroll
        for (int ks = 0; ks < 2; ks++) {
            uint32_t a[4];
            ldm4(a, Ab + ((w * 16 + (l & 15)) * AST + ks * 16 + (l >> 4) * 8) * 2);
            uint32_t bf[2][4];
#pragma unroll
            for (int i = 0; i < 2; i++)
                ldm4(bf[i], Bb + ((i * 16 + (l & 15)) * AST + ks * 16 + (l >> 4) * 8) * 2);
#pragma unroll
            for (int nt = 0; nt < 4; nt++)
                mma16816(c[nt], a, bf[nt >> 1][nt & 1], bf[nt >> 1][(nt & 1) + 2]);
        }
        __syncthreads();
    }

    int g = l >> 2, t2 = (l & 3) * 2;
#pragma unroll
    for (int h = 0; h < 2; h++) {
        int r = mt * 128 + w * 16 + h * 8 + g;
#pragma unroll
        for (int nt = 0; nt < 2; nt++) {
            float v[2];
#pragma unroll
            for (int e = 0; e < 2; e++) {
                int col = nt * 8 + t2 + e;
                float u  = c[nt][2 * h + e] + sb[col];
                float gp = c[nt + 2][2 * h + e] + sb[16 + col];
                v[e] = u / (1.f + expf(-gp));
            }
            *(float2*)(d_gu + (size_t)r * 16 + nt * 8 + t2) = make_float2(v[0], v[1]);
        }
    }
}

// --------------------------------------------------------------------------
// GEMM2: y = x Wskip^T (mma) + hs Wout^T + b_out + b_skip (fp32 epilogue)
// CTA: M=128 (grid.y), N=128 (grid.x=6), K chunks of 32; 8 warps = 4m x 2n
// --------------------------------------------------------------------------
constexpr int G2_A0 = 0;
constexpr int G2_A1 = 10240;
constexpr int G2_B0 = 20480;
constexpr int G2_B1 = 30720;
constexpr int G2_W  = 40960;            // 128*16 f32
constexpr int G2_BI = G2_W + 8192;      // 128 f32
constexpr int G2TOTAL = G2_BI + 512;

__global__ void __launch_bounds__(256, 2) k_gemm2(const float* __restrict__ Wout,
                                                  const float* __restrict__ bout,
                                                  const float* __restrict__ bskip,
                                                  float* __restrict__ y) {
    extern __shared__ char smem[];
    uint32_t sb = smem_u32(smem);
    int tid = threadIdx.x, w = tid >> 5, l = tid & 31;
    int nt = blockIdx.x, mt = blockIdx.y;
    int mw = w >> 1, nw = w & 1;

    float* sW = (float*)(smem + G2_W);
    float* sBias = (float*)(smem + G2_BI);
    for (int i = tid; i < 2048; i += 256) sW[i] = Wout[nt * 2048 + i];
    if (tid < 128) sBias[tid] = bout[nt * 128 + tid] + bskip[nt * 128 + tid];

    const __half* Asrc = d_xh + (size_t)mt * 128 * DIM;
    const __half* Bsrc = d_wsk + (size_t)nt * 128 * DIM;

    auto load_stage = [&](int kc) {
        uint32_t Ad = sb + ((kc & 1) ? G2_A1 : G2_A0);
        uint32_t Bd = sb + ((kc & 1) ? G2_B1 : G2_B0);
#pragma unroll
        for (int q = 0; q < 2; q++) {
            int s = tid + q * 256;
            int row = s >> 2, cs = s & 3;
            cpa16(Ad + (row * AST + cs * 8) * 2, Asrc + (size_t)row * DIM + kc * 32 + cs * 8);
            cpa16(Bd + (row * AST + cs * 8) * 2, Bsrc + (size_t)row * DIM + kc * 32 + cs * 8);
        }
    };

    float c[2][8][4];
#pragma unroll
    for (int i = 0; i < 2; i++)
#pragma unroll
        for (int j = 0; j < 8; j++)
#pragma unroll
            for (int e = 0; e < 4; e++) c[i][j][e] = 0.f;

    load_stage(0);
    cpa_commit();
    for (int kc = 0; kc < 24; kc++) {
        if (kc + 1 < 24) load_stage(kc + 1);
        cpa_commit();
        cpa_wait1();
        __syncthreads();
        uint32_t Ab = sb + ((kc & 1) ? G2_A1 : G2_A0);
        uint32_t Bb = sb + ((kc & 1) ? G2_B1 : G2_B0);
#pragma unroll
        for (int ks = 0; ks < 2; ks++) {
            uint32_t a[2][4];
#pragma unroll
            for (int m2 = 0; m2 < 2; m2++)
                ldm4(a[m2], Ab + ((mw * 32 + m2 * 16 + (l & 15)) * AST + ks * 16 + (l >> 4) * 8) * 2);
            uint32_t bf[4][4];
#pragma unroll
            for (int i = 0; i < 4; i++)
                ldm4(bf[i], Bb + ((nw * 64 + i * 16 + (l & 15)) * AST + ks * 16 + (l >> 4) * 8) * 2);
#pragma unroll
            for (int m2 = 0; m2 < 2; m2++)
#pragma unroll
                for (int n2 = 0; n2 < 8; n2++)
                    mma16816(c[m2][n2], a[m2], bf[n2 >> 1][n2 & 1], bf[n2 >> 1][(n2 & 1) + 2]);
        }
        __syncthreads();
    }

    // epilogue: + bias + hs @ Wout^T
    int g = l >> 2, t2 = (l & 3) * 2;
#pragma unroll
    for (int m2 = 0; m2 < 2; m2++) {
#pragma unroll
        for (int h = 0; h < 2; h++) {
            int r = mt * 128 + mw * 32 + m2 * 16 + h * 8 + g;
            float hs[16];
            const float4* hsrc = (const float4*)(d_gu + (size_t)r * 16);
#pragma unroll
            for (int q = 0; q < 4; q++) {
                float4 vv = hsrc[q];
                hs[4 * q] = vv.x; hs[4 * q + 1] = vv.y; hs[4 * q + 2] = vv.z; hs[4 * q + 3] = vv.w;
            }
            float* yb = y + (size_t)r * DIM + nt * 128;
#pragma unroll
            for (int n2 = 0; n2 < 8; n2++) {
                int col = nw * 64 + n2 * 8 + t2;
                float v[2];
#pragma unroll
                for (int e = 0; e < 2; e++) {
                    float acc = c[m2][n2][2 * h + e] + sBias[col + e];
                    const float* wr = sW + (col + e) * 16;
#pragma unroll
                    for (int n = 0; n < 16; n++) acc += hs[n] * wr[n];
                    v[e] = acc;
                }
                *(float2*)(yb + col) = make_float2(v[0], v[1]);
            }
        }
    }
}

// --------------------------------------------------------------------------
extern "C" void kernel_launch(void* const* d_in, const int* in_sizes, int n_in,
                              void* d_out, int out_size) {
    (void)in_sizes; (void)n_in; (void)out_size;
    const float* x      = (const float*)d_in[0];
    const float* a_log  = (const float*)d_in[1];
    const float* U      = (const float*)d_in[2];
    const float* V      = (const float*)d_in[3];
    const float* Win    = (const float*)d_in[4];
    const float* bin    = (const float*)d_in[5];
    const float* Wgate  = (const float*)d_in[6];
    const float* bgate  = (const float*)d_in[7];
    const float* Wout   = (const float*)d_in[8];
    const float* bout   = (const float*)d_in[9];
    const float* Wskip  = (const float*)d_in[10];
    const float* bskip  = (const float*)d_in[11];
    float* y = (float*)d_out;

    __half *xh, *wsk, *wio;
    cudaGetSymbolAddress((void**)&xh,  d_xh);
    cudaGetSymbolAddress((void**)&wsk, d_wsk);
    cudaGetSymbolAddress((void**)&wio, d_wio);

    cudaFuncSetAttribute(k_gemm2, cudaFuncAttributeMaxDynamicSharedMemorySize, G2TOTAL);

    k_tohalf<<<(ROWS * DIM / 4 + 255) / 256, 256>>>(x, xh, ROWS * DIM / 4);
    k_tohalf<<<(DIM * DIM / 4 + 255) / 256, 256>>>(Wskip, wsk, DIM * DIM / 4);
    k_tohalf<<<(NST * DIM / 4 + 255) / 256, 256>>>(Win, wio, NST * DIM / 4);
    k_tohalf<<<(NST * DIM / 4 + 255) / 256, 256>>>(Wgate, wio + NST * DIM, NST * DIM / 4);
    k_powers<<<1, 256>>>(a_log, U, V);
    k_gemm1<<<ROWS / 128, 256>>>(bin, bgate);
    k_scan_local<<<NTASK / 16, 256>>>();
    k_scan_boundary<<<1, 128>>>();
    k_fixup<<<ROWS * NST / 256, 256>>>();
    k_gemm2<<<dim3(6, 256), 256, G2TOTAL>>>(Wout, bout, bskip, y);
}

// round 4
// speedup vs baseline: 1.0050x; 1.0050x over previous
#include <cuda_runtime.h>
#include <cuda_fp16.h>
#include <cstdint>
#include <cmath>

constexpr int BATCH = 8;
constexpr int SEQ   = 4096;
constexpr int DIM   = 768;
constexpr int NST   = 16;
constexpr int ROWS  = BATCH * SEQ;        // 32768
constexpr int CHUNK = 64;
constexpr int NCHUNK = SEQ / CHUNK;       // 64
constexpr int NTASK  = BATCH * NCHUNK;    // 512

__device__ float  d_gu[ROWS * NST];
__device__ float  d_lend[NTASK * NST];
__device__ float  d_hstart[NTASK * NST];
__device__ float  d_Ppow[CHUNK * NST * NST];
__device__ __half d_xh[ROWS * DIM];           // fp16 x (written by gemm1)
__device__ __half d_wsk[DIM * DIM];           // fp16 W_skip

#define DEVI __device__ __forceinline__

DEVI uint32_t smem_u32(const void* p) {
    uint32_t a;
    asm("{ .reg .u64 t; cvta.to.shared.u64 t, %1; cvt.u32.u64 %0, t; }" : "=r"(a) : "l"(p));
    return a;
}
DEVI void cpa16(uint32_t dst, const void* src) {
    asm volatile("cp.async.ca.shared.global [%0], [%1], 16;" :: "r"(dst), "l"(src));
}
DEVI void cpa_commit() { asm volatile("cp.async.commit_group;"); }
DEVI void cpa_wait2()  { asm volatile("cp.async.wait_group 2;"); }
DEVI void ldm4(uint32_t* r, uint32_t a) {
    asm volatile("ldmatrix.sync.aligned.m8n8.x4.shared.b16 {%0,%1,%2,%3}, [%4];"
                 : "=r"(r[0]), "=r"(r[1]), "=r"(r[2]), "=r"(r[3]) : "r"(a));
}
DEVI void mma16816(float* c, const uint32_t* a, uint32_t b0, uint32_t b1) {
    asm volatile(
        "mma.sync.aligned.m16n8k16.row.col.f32.f16.f16.f32 "
        "{%0,%1,%2,%3},{%4,%5,%6,%7},{%8,%9},{%0,%1,%2,%3};"
        : "+f"(c[0]), "+f"(c[1]), "+f"(c[2]), "+f"(c[3])
        : "r"(a[0]), "r"(a[1]), "r"(a[2]), "r"(a[3]), "r"(b0), "r"(b1));
}

// --------------------------------------------------------------------------
__global__ void __launch_bounds__(256) k_tohalf(const float* __restrict__ s,
                                                __half* __restrict__ d, int n4) {
    int i = blockIdx.x * 256 + threadIdx.x;
    if (i < n4) {
        float4 v = ((const float4*)s)[i];
        ((__half2*)d)[2 * i]     = __floats2half2_rn(v.x, v.y);
        ((__half2*)d)[2 * i + 1] = __floats2half2_rn(v.z, v.w);
    }
}

// --------------------------------------------------------------------------
// Ppow[j] = T^(j+1);  T[n][m] = sigma(a[n])*delta(n,m) + sum_r V[m,r]*U[n,r]
// --------------------------------------------------------------------------
__global__ void __launch_bounds__(256) k_powers(const float* __restrict__ a_logit,
                                                const float* __restrict__ U,
                                                const float* __restrict__ V) {
    __shared__ float Ts[256], cur[256];
    int t = threadIdx.x, n = t >> 4, m = t & 15;
    float acc = 0.f;
#pragma unroll
    for (int r = 0; r < 8; r++) acc += V[m * 8 + r] * U[n * 8 + r];
    if (m == n) acc += 1.f / (1.f + expf(-a_logit[n]));
    Ts[t] = acc; cur[t] = acc; d_Ppow[t] = acc;
    __syncthreads();
    for (int j = 1; j < CHUNK; j++) {
        float s = 0.f;
#pragma unroll
        for (int q = 0; q < 16; q++) s += Ts[n * 16 + q] * cur[q * 16 + m];
        __syncthreads();
        cur[t] = s; d_Ppow[j * 256 + t] = s;
        __syncthreads();
    }
}

__global__ void __launch_bounds__(256) k_scan_local() {
    int tid = threadIdx.x;
    int task = blockIdx.x * 16 + (tid >> 4);
    int n = tid & 15;
    float Trow[16];
#pragma unroll
    for (int m = 0; m < 16; m++) Trow[m] = d_Ppow[n * 16 + m];
    int b = task >> 6, k = task & 63;
    float* g = d_gu + ((size_t)(b * SEQ + k * CHUNK)) * NST;
    float h = 0.f;
    for (int j = 0; j < CHUNK; j++) {
        float hn = g[j * NST + n];
#pragma unroll
        for (int m = 0; m < 16; m++)
            hn += Trow[m] * __shfl_sync(0xffffffffu, h, m, 16);
        h = hn;
        g[j * NST + n] = h;
    }
    d_lend[task * NST + n] = h;
}

__global__ void __launch_bounds__(128) k_scan_boundary() {
    int tid = threadIdx.x;
    int b = tid >> 4, n = tid & 15;
    float TC[16];
#pragma unroll
    for (int m = 0; m < 16; m++) TC[m] = d_Ppow[(CHUNK - 1) * 256 + n * 16 + m];
    float s = 0.f;
    for (int k = 0; k < NCHUNK; k++) {
        int base = (b * NCHUNK + k) * NST;
        d_hstart[base + n] = s;
        float acc = d_lend[base + n];
#pragma unroll
        for (int m = 0; m < 16; m++)
            acc += TC[m] * __shfl_sync(0xffffffffu, s, m, 16);
        s = acc;
    }
}

__global__ void __launch_bounds__(256) k_fixup() {
    int idx = blockIdx.x * 256 + threadIdx.x;
    int r = idx >> 4, n = idx & 15;
    int b = r >> 12, t = r & 4095;
    int k = t >> 6, j = t & 63;
    const float* P = d_Ppow + j * 256 + n * 16;
    const float* s = d_hstart + (b * NCHUNK + k) * NST;
    float acc = d_gu[idx];
#pragma unroll
    for (int m = 0; m < 16; m++) acc += P[m] * s[m];
    d_gu[idx] = acc;
}

// --------------------------------------------------------------------------
// GEMM1: gu = sigmoid(x Wg^T + bg) * (x Wi^T + bi)
// A = fp32 x, converted in-regs -> smem (ldmatrix) + streamed to d_xh.
// B = [W_in; W_gate] fp32 -> fp16 smem once (entire 32x768).
// CTA: M=128, 8 warps (16 rows each, full N=32), K chunks of 32 (24).
// --------------------------------------------------------------------------
constexpr int G1_BS = 776;                           // B row stride (halves)
constexpr int G1_B  = 0;                             // 32*776*2 = 49664 B
constexpr int G1_A  = 49664;                         // 2 * 128*40*2 = 20480 B
constexpr int G1_BIAS = G1_A + 20480;                // 32 f32
constexpr int G1TOTAL = G1_BIAS + 128;
constexpr int AST = 40;                              // A row stride (halves)

__global__ void __launch_bounds__(256, 2) k_gemm1(const float* __restrict__ x,
                                                  const float* __restrict__ Win,
                                                  const float* __restrict__ Wgate,
                                                  const float* __restrict__ bin,
                                                  const float* __restrict__ bgate) {
    extern __shared__ char smem[];
    __half* sBh = (__half*)(smem + G1_B);
    __half* sAh = (__half*)(smem + G1_A);
    float*  sb  = (float*)(smem + G1_BIAS);
    int tid = threadIdx.x, w = tid >> 5, l = tid & 31;
    int mt = blockIdx.x;

    // load whole B (fp32 -> fp16), 32 rows x 768
    for (int i = tid; i < 6144; i += 256) {
        int row = i / 192, c4 = i % 192;
        const float* src = (row < 16) ? (Win + (size_t)row * DIM) : (Wgate + (size_t)(row - 16) * DIM);
        float4 v = ((const float4*)src)[c4];
        *(__half2*)(sBh + row * G1_BS + c4 * 4)     = __floats2half2_rn(v.x, v.y);
        *(__half2*)(sBh + row * G1_BS + c4 * 4 + 2) = __floats2half2_rn(v.z, v.w);
    }
    if (tid < 16) { sb[tid] = bin[tid]; sb[16 + tid] = bgate[tid]; }

    // A register prefetch: thread -> (row = tid/2, half = tid&1) : 16 floats
    int arow = tid >> 1, ahalf = tid & 1;
    const float* Abase = x + (size_t)(mt * 128 + arow) * DIM + ahalf * 16;
    __half* xdst = d_xh + (size_t)(mt * 128 + arow) * DIM + ahalf * 16;

    float4 rg[4];
#pragma unroll
    for (int q = 0; q < 4; q++) rg[q] = ((const float4*)Abase)[q];

    float c[4][4];
#pragma unroll
    for (int i = 0; i < 4; i++)
#pragma unroll
        for (int j = 0; j < 4; j++) c[i][j] = 0.f;

    uint32_t aAddr = smem_u32(sAh);
    uint32_t bAddr = smem_u32(sBh);

    for (int kc = 0; kc < 24; kc++) {
        __syncthreads();
        // convert + store to smem + stream to d_xh
        uint32_t hp[8];
#pragma unroll
        for (int q = 0; q < 4; q++) {
            __half2 h0 = __floats2half2_rn(rg[q].x, rg[q].y);
            __half2 h1 = __floats2half2_rn(rg[q].z, rg[q].w);
            hp[2 * q]     = *(uint32_t*)&h0;
            hp[2 * q + 1] = *(uint32_t*)&h1;
        }
        __half* Ad = sAh + (kc & 1) * (128 * AST) + arow * AST + ahalf * 16;
        *(uint4*)Ad       = make_uint4(hp[0], hp[1], hp[2], hp[3]);
        *(uint4*)(Ad + 8) = make_uint4(hp[4], hp[5], hp[6], hp[7]);
        *(uint4*)(xdst + kc * 32)     = make_uint4(hp[0], hp[1], hp[2], hp[3]);
        *(uint4*)(xdst + kc * 32 + 8) = make_uint4(hp[4], hp[5], hp[6], hp[7]);
        if (kc < 23) {
            const float4* nsrc = (const float4*)(Abase + (kc + 1) * 32);
#pragma unroll
            for (int q = 0; q < 4; q++) rg[q] = nsrc[q];
        }
        __syncthreads();
        uint32_t Ab = aAddr + (kc & 1) * (128 * AST * 2);
        uint32_t Bb = bAddr + kc * 32 * 2;
#pragma unroll
        for (int ks = 0; ks < 2; ks++) {
            uint32_t a[4];
            ldm4(a, Ab + ((w * 16 + (l & 15)) * AST + ks * 16 + (l >> 4) * 8) * 2);
            uint32_t bf[2][4];
#pragma unroll
            for (int i = 0; i < 2; i++)
                ldm4(bf[i], Bb + ((i * 16 + (l & 15)) * G1_BS + ks * 16 + (l >> 4) * 8) * 2);
#pragma unroll
            for (int nt = 0; nt < 4; nt++)
                mma16816(c[nt], a, bf[nt >> 1][nt & 1], bf[nt >> 1][(nt & 1) + 2]);
        }
    }

    int g = l >> 2, t2 = (l & 3) * 2;
#pragma unroll
    for (int h = 0; h < 2; h++) {
        int r = mt * 128 + w * 16 + h * 8 + g;
#pragma unroll
        for (int nt = 0; nt < 2; nt++) {
            float v[2];
#pragma unroll
            for (int e = 0; e < 2; e++) {
                int col = nt * 8 + t2 + e;
                float u  = c[nt][2 * h + e] + sb[col];
                float gp = c[nt + 2][2 * h + e] + sb[16 + col];
                v[e] = u / (1.f + expf(-gp));
            }
            *(float2*)(d_gu + (size_t)r * 16 + nt * 8 + t2) = make_float2(v[0], v[1]);
        }
    }
}

// --------------------------------------------------------------------------
// GEMM2: y = x Wskip^T (mma) + hs Wout^T + b_out + b_skip (fp32 epilogue)
// CTA: M=128 (grid.y=256), N=128 (grid.x=6); 4-stage cp.async pipeline,
// one __syncthreads per K-tile. 8 warps = 4m x 2n.
// --------------------------------------------------------------------------
constexpr int G2_STG = 20480;                 // per stage: A 10240 + B 10240
constexpr int G2_W   = 4 * G2_STG;            // 81920: 128*16 f32
constexpr int G2_BI  = G2_W + 8192;           // 128 f32
constexpr int G2TOTAL = G2_BI + 512;          // 90624

__global__ void __launch_bounds__(256, 2) k_gemm2(const float* __restrict__ Wout,
                                                  const float* __restrict__ bout,
                                                  const float* __restrict__ bskip,
                                                  float* __restrict__ y) {
    extern __shared__ char smem[];
    uint32_t sb = smem_u32(smem);
    int tid = threadIdx.x, w = tid >> 5, l = tid & 31;
    int nt = blockIdx.x, mt = blockIdx.y;
    int mw = w >> 1, nw = w & 1;

    float* sW = (float*)(smem + G2_W);
    float* sBias = (float*)(smem + G2_BI);
    for (int i = tid; i < 2048; i += 256) sW[i] = Wout[nt * 2048 + i];
    if (tid < 128) sBias[tid] = bout[nt * 128 + tid] + bskip[nt * 128 + tid];

    const __half* Asrc = d_xh + (size_t)mt * 128 * DIM;
    const __half* Bsrc = d_wsk + (size_t)nt * 128 * DIM;

    auto load_stage = [&](int kc) {
        uint32_t Ad = sb + (kc & 3) * G2_STG;
        uint32_t Bd = Ad + 10240;
#pragma unroll
        for (int q = 0; q < 2; q++) {
            int s = tid + q * 256;
            int row = s >> 2, cs = s & 3;
            cpa16(Ad + (row * AST + cs * 8) * 2, Asrc + (size_t)row * DIM + kc * 32 + cs * 8);
            cpa16(Bd + (row * AST + cs * 8) * 2, Bsrc + (size_t)row * DIM + kc * 32 + cs * 8);
        }
    };

    float c[2][8][4];
#pragma unroll
    for (int i = 0; i < 2; i++)
#pragma unroll
        for (int j = 0; j < 8; j++)
#pragma unroll
            for (int e = 0; e < 4; e++) c[i][j][e] = 0.f;

    load_stage(0); cpa_commit();
    load_stage(1); cpa_commit();

    for (int kc = 0; kc < 24; kc++) {
        if (kc + 2 < 24) load_stage(kc + 2);
        cpa_commit();
        cpa_wait2();
        __syncthreads();
        uint32_t Ab = sb + (kc & 3) * G2_STG;
        uint32_t Bb = Ab + 10240;
#pragma unroll
        for (int ks = 0; ks < 2; ks++) {
            uint32_t a[2][4];
#pragma unroll
            for (int m2 = 0; m2 < 2; m2++)
                ldm4(a[m2], Ab + ((mw * 32 + m2 * 16 + (l & 15)) * AST + ks * 16 + (l >> 4) * 8) * 2);
            uint32_t bf[4][4];
#pragma unroll
            for (int i = 0; i < 4; i++)
                ldm4(bf[i], Bb + ((nw * 64 + i * 16 + (l & 15)) * AST + ks * 16 + (l >> 4) * 8) * 2);
#pragma unroll
            for (int m2 = 0; m2 < 2; m2++)
#pragma unroll
                for (int n2 = 0; n2 < 8; n2++)
                    mma16816(c[m2][n2], a[m2], bf[n2 >> 1][n2 & 1], bf[n2 >> 1][(n2 & 1) + 2]);
        }
    }

    int g = l >> 2, t2 = (l & 3) * 2;
#pragma unroll
    for (int m2 = 0; m2 < 2; m2++) {
#pragma unroll
        for (int h = 0; h < 2; h++) {
            int r = mt * 128 + mw * 32 + m2 * 16 + h * 8 + g;
            float hs[16];
            const float4* hsrc = (const float4*)(d_gu + (size_t)r * 16);
#pragma unroll
            for (int q = 0; q < 4; q++) {
                float4 vv = hsrc[q];
                hs[4 * q] = vv.x; hs[4 * q + 1] = vv.y; hs[4 * q + 2] = vv.z; hs[4 * q + 3] = vv.w;
            }
            float* yb = y + (size_t)r * DIM + nt * 128;
#pragma unroll
            for (int n2 = 0; n2 < 8; n2++) {
                int col = nw * 64 + n2 * 8 + t2;
                float v[2];
#pragma unroll
                for (int e = 0; e < 2; e++) {
                    float acc = c[m2][n2][2 * h + e] + sBias[col + e];
                    const float* wr = sW + (col + e) * 16;
#pragma unroll
                    for (int n = 0; n < 16; n++) acc += hs[n] * wr[n];
                    v[e] = acc;
                }
                *(float2*)(yb + col) = make_float2(v[0], v[1]);
            }
        }
    }
}

// --------------------------------------------------------------------------
extern "C" void kernel_launch(void* const* d_in, const int* in_sizes, int n_in,
                              void* d_out, int out_size) {
    (void)in_sizes; (void)n_in; (void)out_size;
    const float* x      = (const float*)d_in[0];
    const float* a_log  = (const float*)d_in[1];
    const float* U      = (const float*)d_in[2];
    const float* V      = (const float*)d_in[3];
    const float* Win    = (const float*)d_in[4];
    const float* bin    = (const float*)d_in[5];
    const float* Wgate  = (const float*)d_in[6];
    const float* bgate  = (const float*)d_in[7];
    const float* Wout   = (const float*)d_in[8];
    const float* bout   = (const float*)d_in[9];
    const float* Wskip  = (const float*)d_in[10];
    const float* bskip  = (const float*)d_in[11];
    float* y = (float*)d_out;

    __half* wsk;
    cudaGetSymbolAddress((void**)&wsk, d_wsk);

    cudaFuncSetAttribute(k_gemm1, cudaFuncAttributeMaxDynamicSharedMemorySize, G1TOTAL);
    cudaFuncSetAttribute(k_gemm2, cudaFuncAttributeMaxDynamicSharedMemorySize, G2TOTAL);

    k_tohalf<<<(DIM * DIM / 4 + 255) / 256, 256>>>(Wskip, wsk, DIM * DIM / 4);
    k_powers<<<1, 256>>>(a_log, U, V);
    k_gemm1<<<ROWS / 128, 256, G1TOTAL>>>(x, Win, Wgate, bin, bgate);
    k_scan_local<<<NTASK / 16, 256>>>();
    k_scan_boundary<<<1, 128>>>();
    k_fixup<<<ROWS * NST / 256, 256>>>();
    k_gemm2<<<dim3(6, 256), 256, G2TOTAL>>>(Wout, bout, bskip, y);
}